// round 4
// baseline (speedup 1.0000x reference)
#include <cuda_runtime.h>
#include <cuda_bf16.h>
#include <math.h>

// ---------------- problem constants ----------------
#define KBINS 125
#define N0 131072
#define N1 65536
#define N2 32768
#define N3 16384
#define B8 16384
#define E1 1703936
#define E2 851968
#define E3 425984
#define NBATCH 2048

// ---------------- static scratch (no allocation allowed) ----------------
__device__ float g_p0[N1];          // pooled level-1 input (cin=1)
__device__ float g_a1[N1 * 32];
__device__ float g_h1[N1 * 32];
__device__ float g_deg1[N1];
__device__ float g_p1[N2 * 32];
__device__ float g_a2[N2 * 32];
__device__ float g_h2[N2 * 32];
__device__ float g_deg2[N2];
__device__ float g_p2[N3 * 32];
__device__ float g_a3[N3 * 32];
__device__ float g_h3[N3 * 32];
__device__ float g_deg3[N3];
__device__ float g_p3[B8 * 32];
__device__ float g_Wt2[KBINS * 32 * 32];   // W2 transposed: [k][o][i]
__device__ float g_Wt3[KBINS * 32 * 32];   // W3 transposed: [k][o][i]

// ---- device-side selectors (all global-array addressing stays in device code) ----
template <int L> __device__ __forceinline__ float* pool_in();
template <> __device__ __forceinline__ float* pool_in<1>() { return g_h1; }
template <> __device__ __forceinline__ float* pool_in<2>() { return g_h2; }
template <> __device__ __forceinline__ float* pool_in<3>() { return g_h3; }

template <int L> __device__ __forceinline__ float* pool_out();
template <> __device__ __forceinline__ float* pool_out<1>() { return g_p1; }
template <> __device__ __forceinline__ float* pool_out<2>() { return g_p2; }
template <> __device__ __forceinline__ float* pool_out<3>() { return g_p3; }

template <int L> __device__ __forceinline__ float* conv_h();
template <> __device__ __forceinline__ float* conv_h<2>() { return g_p1; }
template <> __device__ __forceinline__ float* conv_h<3>() { return g_p2; }

template <int L> __device__ __forceinline__ float* conv_Wt();
template <> __device__ __forceinline__ float* conv_Wt<2>() { return g_Wt2; }
template <> __device__ __forceinline__ float* conv_Wt<3>() { return g_Wt3; }

template <int L> __device__ __forceinline__ float* conv_agg();
template <> __device__ __forceinline__ float* conv_agg<2>() { return g_a2; }
template <> __device__ __forceinline__ float* conv_agg<3>() { return g_a3; }

template <int L> __device__ __forceinline__ float* conv_deg();
template <> __device__ __forceinline__ float* conv_deg<2>() { return g_deg2; }
template <> __device__ __forceinline__ float* conv_deg<3>() { return g_deg3; }

template <int L> __device__ __forceinline__ float* fin_hout();
template <> __device__ __forceinline__ float* fin_hout<2>() { return g_h2; }
template <> __device__ __forceinline__ float* fin_hout<3>() { return g_h3; }

template <int L> struct LayerE;
template <> struct LayerE<2> { static const int E = E2; static const int NIN = N2; };
template <> struct LayerE<3> { static const int E = E3; static const int NIN = N3; };

// ---------------- helpers ----------------
__device__ __forceinline__ void atomicMaxF(float* addr, float v) {
    // monotone float-max via int/uint atomics (valid across mixed signs, -inf init)
    if (__float_as_int(v) >= 0) {
        atomicMax((int*)addr, __float_as_int(v));
    } else {
        atomicMin((unsigned int*)addr, __float_as_uint(v));
    }
}

// ---------------- init (references globals directly) ----------------
__global__ void k_init_all() {
    int i = blockIdx.x * blockDim.x + threadIdx.x;
    int stride = gridDim.x * blockDim.x;
    const float NEGINF = -INFINITY;
    for (int j = i; j < N1; j += stride)      { g_p0[j] = NEGINF; g_deg1[j] = 0.0f; }
    for (int j = i; j < N1 * 32; j += stride) g_a1[j] = 0.0f;
    for (int j = i; j < N2 * 32; j += stride) { g_p1[j] = NEGINF; g_a2[j] = 0.0f; }
    for (int j = i; j < N2; j += stride)      g_deg2[j] = 0.0f;
    for (int j = i; j < N3 * 32; j += stride) { g_p2[j] = NEGINF; g_a3[j] = 0.0f; }
    for (int j = i; j < N3; j += stride)      g_deg3[j] = 0.0f;
    for (int j = i; j < B8 * 32; j += stride) g_p3[j] = NEGINF;
}

__global__ void k_transposeW(const float* __restrict__ W2, const float* __restrict__ W3) {
    // W [125][32][32] (i,o) -> Wt [125][32][32] (o,i)
    int idx = blockIdx.x * blockDim.x + threadIdx.x;
    if (idx >= KBINS * 1024) return;
    int k = idx >> 10;
    int r = idx & 1023;
    int i = r >> 5;
    int o = r & 31;
    g_Wt2[k * 1024 + o * 32 + i] = __ldg(&W2[idx]);
    g_Wt3[k * 1024 + o * 32 + i] = __ldg(&W3[idx]);
}

// ---------------- pools ----------------
__global__ void k_pool0(const float* __restrict__ x, const int* __restrict__ cluster) {
    int i = blockIdx.x * blockDim.x + threadIdx.x;
    if (i >= N0) return;
    atomicMaxF(&g_p0[__ldg(&cluster[i])], __ldg(&x[i]));
}
__global__ void k_fix0() {
    int i = blockIdx.x * blockDim.x + threadIdx.x;
    if (i < N1 && !isfinite(g_p0[i])) g_p0[i] = 0.0f;
}

template <int L>
__global__ void k_pool32(const int* __restrict__ cluster, int n_in) {
    int i = blockIdx.x * blockDim.x + threadIdx.x;
    if (i >= n_in * 32) return;
    int node = i >> 5;
    int ch = i & 31;
    atomicMaxF(&pool_out<L>()[(size_t)__ldg(&cluster[node]) * 32 + ch], pool_in<L>()[i]);
}

template <int L>
__global__ void k_fix32(int n) {
    int i = blockIdx.x * blockDim.x + threadIdx.x;
    if (i < n) {
        float v = pool_out<L>()[i];
        if (!isfinite(v)) pool_out<L>()[i] = 0.0f;
    }
}

// ---------------- spline basis ----------------
struct Basis {
    float f0, f1, f2;
    int i0, i1, i2;
};

__device__ __forceinline__ Basis spline_basis(const float* __restrict__ pseudo, int e) {
    Basis b;
    float v0 = __ldg(&pseudo[e * 3 + 0]) * 4.0f;
    float v1 = __ldg(&pseudo[e * 3 + 1]) * 4.0f;
    float v2 = __ldg(&pseudo[e * 3 + 2]) * 4.0f;
    float k0 = fminf(fmaxf(floorf(v0), 0.0f), 3.0f);
    float k1 = fminf(fmaxf(floorf(v1), 0.0f), 3.0f);
    float k2 = fminf(fmaxf(floorf(v2), 0.0f), 3.0f);
    b.f0 = v0 - k0; b.f1 = v1 - k1; b.f2 = v2 - k2;
    b.i0 = (int)k0; b.i1 = (int)k1; b.i2 = (int)k2;
    return b;
}

// ---------------- conv layer 1 (cin = 1), warp per edge ----------------
__global__ void k_edge_conv1(const int* __restrict__ ei, const float* __restrict__ pseudo,
                             const float* __restrict__ W1) {
    int g = blockIdx.x * blockDim.x + threadIdx.x;
    int e = g >> 5;
    int lane = g & 31;
    if (e >= E1) return;
    int src = __ldg(&ei[e]);
    int dst = __ldg(&ei[E1 + e]);
    Basis b = spline_basis(pseudo, e);
    float xj = g_p0[src];

    float acc = 0.0f;
#pragma unroll
    for (int c = 0; c < 8; c++) {
        int o0 = c & 1, o1 = (c >> 1) & 1, o2 = (c >> 2) & 1;
        float wc = (o0 ? b.f0 : 1.0f - b.f0) * (o1 ? b.f1 : 1.0f - b.f1) * (o2 ? b.f2 : 1.0f - b.f2);
        int flat = ((b.i0 + o0) * 5 + (b.i1 + o1)) * 5 + (b.i2 + o2);
        acc += wc * __ldg(&W1[flat * 32 + lane]);   // W1 [125][1][32]
    }
    atomicAdd(&g_a1[(size_t)dst * 32 + lane], xj * acc);
    if (lane == 0) atomicAdd(&g_deg1[dst], 1.0f);
}

// ---------------- conv layers 2/3 (cin = 32), warp per edge ----------------
template <int L>
__global__ void k_edge_conv32(const int* __restrict__ ei, const float* __restrict__ pseudo) {
    const int E = LayerE<L>::E;
    int g = blockIdx.x * blockDim.x + threadIdx.x;
    int e = g >> 5;
    int lane = g & 31;
    if (e >= E) return;
    int src = __ldg(&ei[e]);
    int dst = __ldg(&ei[E + e]);
    Basis b = spline_basis(pseudo, e);

    // broadcast-load neighbor feature vector (32 floats) into registers
    const float4* xp = (const float4*)(conv_h<L>() + (size_t)src * 32);
    float4 xv[8];
#pragma unroll
    for (int q = 0; q < 8; q++) xv[q] = xp[q];

    const float* Wt = conv_Wt<L>();
    float acc = 0.0f;
#pragma unroll
    for (int c = 0; c < 8; c++) {
        int o0 = c & 1, o1 = (c >> 1) & 1, o2 = (c >> 2) & 1;
        float wc = (o0 ? b.f0 : 1.0f - b.f0) * (o1 ? b.f1 : 1.0f - b.f1) * (o2 ? b.f2 : 1.0f - b.f2);
        int flat = ((b.i0 + o0) * 5 + (b.i1 + o1)) * 5 + (b.i2 + o2);
        const float4* wp = (const float4*)(Wt + flat * 1024 + lane * 32);  // Wt [k][o][i]
        float t = 0.0f;
#pragma unroll
        for (int q = 0; q < 8; q++) {
            float4 wv = wp[q];
            t += wv.x * xv[q].x + wv.y * xv[q].y + wv.z * xv[q].z + wv.w * xv[q].w;
        }
        acc += wc * t;
    }
    atomicAdd(&conv_agg<L>()[(size_t)dst * 32 + lane], acc);
    if (lane == 0) atomicAdd(&conv_deg<L>()[dst], 1.0f);
}

// ---------------- finalize: /deg + x@root + b, ELU ----------------
__global__ void k_finalize1(const float* __restrict__ root, const float* __restrict__ bias) {
    int g = blockIdx.x * blockDim.x + threadIdx.x;
    int node = g >> 5, lane = g & 31;
    if (node >= N1) return;
    float r = g_p0[node] * __ldg(&root[lane]);            // root1 [1][32]
    float d = fmaxf(g_deg1[node], 1.0f);
    float v = g_a1[(size_t)node * 32 + lane] / d + r + __ldg(&bias[lane]);
    g_h1[(size_t)node * 32 + lane] = v > 0.0f ? v : expm1f(v);
}

template <int L>
__global__ void k_finalize32(const float* __restrict__ root, const float* __restrict__ bias) {
    const int n = LayerE<L>::NIN;
    int g = blockIdx.x * blockDim.x + threadIdx.x;
    int node = g >> 5, lane = g & 31;
    if (node >= n) return;
    const float4* hp = (const float4*)(conv_h<L>() + (size_t)node * 32);
    float r = 0.0f;
#pragma unroll
    for (int q = 0; q < 8; q++) {
        float4 hv = hp[q];
        r += hv.x * __ldg(&root[(4 * q + 0) * 32 + lane]);
        r += hv.y * __ldg(&root[(4 * q + 1) * 32 + lane]);
        r += hv.z * __ldg(&root[(4 * q + 2) * 32 + lane]);
        r += hv.w * __ldg(&root[(4 * q + 3) * 32 + lane]);
    }
    float d = fmaxf(conv_deg<L>()[node], 1.0f);
    float v = conv_agg<L>()[(size_t)node * 32 + lane] / d + r + __ldg(&bias[lane]);
    fin_hout<L>()[(size_t)node * 32 + lane] = v > 0.0f ? v : expm1f(v);
}

// ---------------- FC head + log_softmax ----------------
__global__ void k_fc_head(const float* __restrict__ fcw, const float* __restrict__ fcb,
                          float* __restrict__ out) {
    __shared__ float hs[256];
    __shared__ float lg[10];
    __shared__ float lse;
    int b = blockIdx.x;
    int t = threadIdx.x;
    hs[t] = g_p3[(size_t)b * 256 + t];
    __syncthreads();
    if (t < 10) {
        float s = __ldg(&fcb[t]);
#pragma unroll 8
        for (int i = 0; i < 256; i++) s += hs[i] * __ldg(&fcw[i * 10 + t]);
        lg[t] = s;
    }
    __syncthreads();
    if (t == 0) {
        float m = lg[0];
        for (int j = 1; j < 10; j++) m = fmaxf(m, lg[j]);
        float se = 0.0f;
        for (int j = 0; j < 10; j++) se += expf(lg[j] - m);
        lse = m + logf(se);
    }
    __syncthreads();
    if (t < 10) out[b * 10 + t] = lg[t] - lse;
}

// ---------------- launcher ----------------
static inline int cdiv(long long a, int b) { return (int)((a + b - 1) / b); }

extern "C" void kernel_launch(void* const* d_in, const int* in_sizes, int n_in,
                              void* d_out, int out_size) {
    const float* x        = (const float*)d_in[0];
    const int*   cluster0 = (const int*)d_in[1];
    const int*   ei1      = (const int*)d_in[2];
    const float* pseudo1  = (const float*)d_in[3];
    const int*   cluster1 = (const int*)d_in[4];
    const int*   ei2      = (const int*)d_in[5];
    const float* pseudo2  = (const float*)d_in[6];
    const int*   cluster2 = (const int*)d_in[7];
    const int*   ei3      = (const int*)d_in[8];
    const float* pseudo3  = (const float*)d_in[9];
    const int*   cluster3 = (const int*)d_in[10];
    const float* W1       = (const float*)d_in[11];
    const float* root1    = (const float*)d_in[12];
    const float* b1       = (const float*)d_in[13];
    const float* W2       = (const float*)d_in[14];
    const float* root2    = (const float*)d_in[15];
    const float* b2       = (const float*)d_in[16];
    const float* W3       = (const float*)d_in[17];
    const float* root3    = (const float*)d_in[18];
    const float* b3       = (const float*)d_in[19];
    const float* fcw      = (const float*)d_in[20];
    const float* fcb      = (const float*)d_in[21];
    float* out = (float*)d_out;

    const int TB = 256;

    // init + weight transposes
    k_init_all<<<1024, TB>>>();
    k_transposeW<<<cdiv(KBINS * 1024, TB), TB>>>(W2, W3);

    // ---- level 1: pool0 (N0 -> N1, C=1) ----
    k_pool0<<<cdiv(N0, TB), TB>>>(x, cluster0);
    k_fix0<<<cdiv(N1, TB), TB>>>();

    // conv1
    k_edge_conv1<<<cdiv((long long)E1 * 32, TB), TB>>>(ei1, pseudo1, W1);
    k_finalize1<<<cdiv(N1 * 32, TB), TB>>>(root1, b1);

    // ---- level 2: pool1 (N1 -> N2, C=32) ----
    k_pool32<1><<<cdiv(N1 * 32, TB), TB>>>(cluster1, N1);
    k_fix32<1><<<cdiv(N2 * 32, TB), TB>>>(N2 * 32);

    // conv2
    k_edge_conv32<2><<<cdiv((long long)E2 * 32, TB), TB>>>(ei2, pseudo2);
    k_finalize32<2><<<cdiv(N2 * 32, TB), TB>>>(root2, b2);

    // ---- level 3: pool2 (N2 -> N3, C=32) ----
    k_pool32<2><<<cdiv(N2 * 32, TB), TB>>>(cluster2, N2);
    k_fix32<2><<<cdiv(N3 * 32, TB), TB>>>(N3 * 32);

    // conv3
    k_edge_conv32<3><<<cdiv((long long)E3 * 32, TB), TB>>>(ei3, pseudo3);
    k_finalize32<3><<<cdiv(N3 * 32, TB), TB>>>(root3, b3);

    // ---- final pool (N3 -> B8, C=32) ----
    k_pool32<3><<<cdiv(N3 * 32, TB), TB>>>(cluster3, N3);
    k_fix32<3><<<cdiv(B8 * 32, TB), TB>>>(B8 * 32);

    // ---- FC + log_softmax ----
    k_fc_head<<<NBATCH, 256>>>(fcw, fcb, out);
}

// round 6
// speedup vs baseline: 5.8850x; 5.8850x over previous
#include <cuda_runtime.h>
#include <cuda_bf16.h>
#include <math.h>

// ---------------- problem constants ----------------
#define KBINS 125
#define N0 131072
#define N1 65536
#define N2 32768
#define N3 16384
#define B8 16384
#define E1 1703936
#define E2 851968
#define E3 425984
#define NBATCH 2048

// ---------------- static scratch ----------------
__device__ float g_p0[N1];
__device__ float g_h1[N1 * 32];
__device__ float g_p1[N2 * 32];
__device__ float g_h2[N2 * 32];
__device__ float g_p2[N3 * 32];
__device__ float g_h3[N3 * 32];
__device__ float g_p3[B8 * 32];

__device__ float g_H1[(size_t)N1 * KBINS];            // 32 MB
__device__ float g_H2[(size_t)N2 * KBINS * 32];       // 524 MB
__device__ float g_H3[(size_t)N3 * KBINS * 32];       // 262 MB

__device__ int    g_cnt1[N1]; __device__ int g_off1[N1 + 1]; __device__ int g_cur1[N1];
__device__ int    g_cnt2[N2]; __device__ int g_off2[N2 + 1]; __device__ int g_cur2[N2];
__device__ int    g_cnt3[N3]; __device__ int g_off3[N3 + 1]; __device__ int g_cur3[N3];
__device__ int    g_src1[E1]; __device__ float4 g_ps1[E1];
__device__ int    g_src2[E2]; __device__ float4 g_ps2[E2];
__device__ int    g_src3[E3]; __device__ float4 g_ps3[E3];

// ---------------- layer traits (all global addressing stays device-side) ----------------
template <int L> struct BT;
template <> struct BT<1> {
    static const int N = N1, E = E1;
    static __device__ __forceinline__ int*    cnt()  { return g_cnt1; }
    static __device__ __forceinline__ int*    off()  { return g_off1; }
    static __device__ __forceinline__ int*    cur()  { return g_cur1; }
    static __device__ __forceinline__ int*    srcS() { return g_src1; }
    static __device__ __forceinline__ float4* psS()  { return g_ps1; }
    static __device__ __forceinline__ float*  H()    { return g_H1; }
    static __device__ __forceinline__ float*  hin()  { return g_p0; }
    static __device__ __forceinline__ float*  hout() { return g_h1; }
};
template <> struct BT<2> {
    static const int N = N2, E = E2;
    static __device__ __forceinline__ int*    cnt()  { return g_cnt2; }
    static __device__ __forceinline__ int*    off()  { return g_off2; }
    static __device__ __forceinline__ int*    cur()  { return g_cur2; }
    static __device__ __forceinline__ int*    srcS() { return g_src2; }
    static __device__ __forceinline__ float4* psS()  { return g_ps2; }
    static __device__ __forceinline__ float*  H()    { return g_H2; }
    static __device__ __forceinline__ float*  hin()  { return g_p1; }
    static __device__ __forceinline__ float*  hout() { return g_h2; }
};
template <> struct BT<3> {
    static const int N = N3, E = E3;
    static __device__ __forceinline__ int*    cnt()  { return g_cnt3; }
    static __device__ __forceinline__ int*    off()  { return g_off3; }
    static __device__ __forceinline__ int*    cur()  { return g_cur3; }
    static __device__ __forceinline__ int*    srcS() { return g_src3; }
    static __device__ __forceinline__ float4* psS()  { return g_ps3; }
    static __device__ __forceinline__ float*  H()    { return g_H3; }
    static __device__ __forceinline__ float*  hin()  { return g_p2; }
    static __device__ __forceinline__ float*  hout() { return g_h3; }
};

// pool selectors
template <int L> __device__ __forceinline__ float* pool_in();
template <> __device__ __forceinline__ float* pool_in<1>() { return g_h1; }
template <> __device__ __forceinline__ float* pool_in<2>() { return g_h2; }
template <> __device__ __forceinline__ float* pool_in<3>() { return g_h3; }
template <int L> __device__ __forceinline__ float* pool_out();
template <> __device__ __forceinline__ float* pool_out<1>() { return g_p1; }
template <> __device__ __forceinline__ float* pool_out<2>() { return g_p2; }
template <> __device__ __forceinline__ float* pool_out<3>() { return g_p3; }

// ---------------- helpers ----------------
__device__ __forceinline__ void atomicMaxF(float* addr, float v) {
    if (__float_as_int(v) >= 0) atomicMax((int*)addr, __float_as_int(v));
    else                        atomicMin((unsigned int*)addr, __float_as_uint(v));
}

__device__ __forceinline__ void basis8(float px, float py, float pz, float* wc, int* flat) {
    float v0 = px * 4.0f, v1 = py * 4.0f, v2 = pz * 4.0f;
    float k0 = fminf(fmaxf(floorf(v0), 0.0f), 3.0f);
    float k1 = fminf(fmaxf(floorf(v1), 0.0f), 3.0f);
    float k2 = fminf(fmaxf(floorf(v2), 0.0f), 3.0f);
    float f0 = v0 - k0, f1 = v1 - k1, f2 = v2 - k2;
    int i0 = (int)k0, i1 = (int)k1, i2 = (int)k2;
#pragma unroll
    for (int c = 0; c < 8; c++) {
        int o0 = c & 1, o1 = (c >> 1) & 1, o2 = (c >> 2) & 1;
        wc[c] = (o0 ? f0 : 1.0f - f0) * (o1 ? f1 : 1.0f - f1) * (o2 ? f2 : 1.0f - f2);
        flat[c] = ((i0 + o0) * 5 + (i1 + o1)) * 5 + (i2 + o2);
    }
}

// ---------------- init ----------------
__global__ void k_init_all() {
    int i = blockIdx.x * blockDim.x + threadIdx.x;
    int stride = gridDim.x * blockDim.x;
    const float NEGINF = -INFINITY;
    for (int j = i; j < N1; j += stride)      { g_p0[j] = NEGINF; g_cnt1[j] = 0; }
    for (int j = i; j < N2 * 32; j += stride) g_p1[j] = NEGINF;
    for (int j = i; j < N2; j += stride)      g_cnt2[j] = 0;
    for (int j = i; j < N3 * 32; j += stride) g_p2[j] = NEGINF;
    for (int j = i; j < N3; j += stride)      g_cnt3[j] = 0;
    for (int j = i; j < B8 * 32; j += stride) g_p3[j] = NEGINF;
}

// ---------------- pools ----------------
__global__ void k_pool0(const float* __restrict__ x, const int* __restrict__ cluster) {
    int i = blockIdx.x * blockDim.x + threadIdx.x;
    if (i >= N0) return;
    atomicMaxF(&g_p0[__ldg(&cluster[i])], __ldg(&x[i]));
}
__global__ void k_fix0() {
    int i = blockIdx.x * blockDim.x + threadIdx.x;
    if (i < N1 && !isfinite(g_p0[i])) g_p0[i] = 0.0f;
}
template <int L>
__global__ void k_pool32(const int* __restrict__ cluster, int n_in) {
    int i = blockIdx.x * blockDim.x + threadIdx.x;
    if (i >= n_in * 32) return;
    int node = i >> 5, ch = i & 31;
    atomicMaxF(&pool_out<L>()[(size_t)__ldg(&cluster[node]) * 32 + ch], pool_in<L>()[i]);
}
template <int L>
__global__ void k_fix32(int n) {
    int i = blockIdx.x * blockDim.x + threadIdx.x;
    if (i < n) {
        float v = pool_out<L>()[i];
        if (!isfinite(v)) pool_out<L>()[i] = 0.0f;
    }
}

// ---------------- CSR build ----------------
template <int L>
__global__ void k_hist(const int* __restrict__ ei) {
    const int E = BT<L>::E;
    int i = blockIdx.x * blockDim.x + threadIdx.x;
    if (i >= E) return;
    atomicAdd(&BT<L>::cnt()[__ldg(&ei[E + i])], 1);
}

template <int L>
__global__ void k_scan() {
    const int N = BT<L>::N;
    const int CH = N / 1024;
    __shared__ int sums[1024];
    int t = threadIdx.x;
    int base = t * CH;
    int s = 0;
    for (int j = 0; j < CH; j++) s += BT<L>::cnt()[base + j];
    sums[t] = s;
    __syncthreads();
    for (int d = 1; d < 1024; d <<= 1) {
        int v = (t >= d) ? sums[t - d] : 0;
        __syncthreads();
        sums[t] += v;
        __syncthreads();
    }
    int run = sums[t] - s;   // exclusive prefix
    for (int j = 0; j < CH; j++) {
        BT<L>::off()[base + j] = run;
        BT<L>::cur()[base + j] = run;
        run += BT<L>::cnt()[base + j];
    }
    if (t == 1023) BT<L>::off()[N] = run;
}

template <int L>
__global__ void k_permscat(const int* __restrict__ ei, const float* __restrict__ pseudo) {
    const int E = BT<L>::E;
    int i = blockIdx.x * blockDim.x + threadIdx.x;
    if (i >= E) return;
    int dst = __ldg(&ei[E + i]);
    int pos = atomicAdd(&BT<L>::cur()[dst], 1);
    BT<L>::srcS()[pos] = __ldg(&ei[i]);
    BT<L>::psS()[pos] = make_float4(__ldg(&pseudo[3 * i]), __ldg(&pseudo[3 * i + 1]),
                                    __ldg(&pseudo[3 * i + 2]), 0.0f);
}

// ---------------- conv1 (cin=1): scatter + contraction ----------------
__global__ void k_scatter1() {
    __shared__ float Hs[8][KBINS];
    int w = threadIdx.x >> 5, lane = threadIdx.x & 31;
    int node = blockIdx.x * 8 + w;
    for (int j = lane; j < KBINS; j += 32) Hs[w][j] = 0.0f;
    __syncwarp();
    int beg = g_off1[node], end = g_off1[node + 1];
    for (int e0 = beg; e0 < end; e0 += 32) {
        int e = e0 + lane;
        if (e < end) {
            int src = g_src1[e];
            float4 ps = g_ps1[e];
            float xj = g_p0[src];
            float wc[8]; int flat[8];
            basis8(ps.x, ps.y, ps.z, wc, flat);
#pragma unroll
            for (int c = 0; c < 8; c++) atomicAdd(&Hs[w][flat[c]], wc[c] * xj);
        }
    }
    __syncwarp();
    for (int j = lane; j < KBINS; j += 32) g_H1[(size_t)node * KBINS + j] = Hs[w][j];
}

__global__ void k_gemm1(const float* __restrict__ W1, const float* __restrict__ root1,
                        const float* __restrict__ b1) {
    __shared__ float W1s[KBINS * 32];
    int tid = threadIdx.x;
    for (int idx = tid; idx < KBINS * 32; idx += 256) W1s[idx] = __ldg(&W1[idx]);
    __syncthreads();
    int w = tid >> 5, lane = tid & 31;
    int node = blockIdx.x * 8 + w;
    const float* Hrow = &g_H1[(size_t)node * KBINS];
    float acc = 0.0f;
#pragma unroll 5
    for (int k = 0; k < KBINS; k++) acc += Hrow[k] * W1s[k * 32 + lane];
    int deg = g_off1[node + 1] - g_off1[node];
    float d = (float)(deg > 0 ? deg : 1);
    float v = acc / d + g_p0[node] * __ldg(&root1[lane]) + __ldg(&b1[lane]);
    g_h1[(size_t)node * 32 + lane] = v > 0.0f ? v : expm1f(v);
}

// ---------------- conv2/3 (cin=32): scatter (warp-per-node, smem row) ----------------
template <int L>
__global__ void k_scatter32() {
    __shared__ float Hs[2][KBINS * 32];
    int w = threadIdx.x >> 5, lane = threadIdx.x & 31;
    int node = blockIdx.x * 2 + w;
    float* hrow = Hs[w];
    for (int j = lane; j < KBINS * 32; j += 32) hrow[j] = 0.0f;
    __syncwarp();
    const float* hin = BT<L>::hin();
    int beg = BT<L>::off()[node], end = BT<L>::off()[node + 1];
    for (int e = beg; e < end; e++) {
        int src = BT<L>::srcS()[e];          // uniform
        float4 ps = BT<L>::psS()[e];         // uniform
        float xv = hin[(size_t)src * 32 + lane];  // coalesced gather
        float wc[8]; int flat[8];
        basis8(ps.x, ps.y, ps.z, wc, flat);
#pragma unroll
        for (int c = 0; c < 8; c++) hrow[flat[c] * 32 + lane] += wc[c] * xv;
    }
    __syncwarp();
    float* Hg = BT<L>::H() + (size_t)node * (KBINS * 32);
    for (int j = lane; j < KBINS * 32; j += 32) Hg[j] = hrow[j];
}

// ---------------- conv2/3 contraction: 64 nodes/block, W streamed through smem ----------------
template <int L>
__global__ void k_gemm32(const float* __restrict__ W, const float* __restrict__ root,
                         const float* __restrict__ bias) {
    __shared__ float Ws[1024];       // W[k]: [i][o] (native layout)
    __shared__ float Hs[64 * 32];    // 64 node-rows of 32
    int tid = threadIdx.x;
    int w = tid >> 5, lane = tid & 31;
    size_t nodeBase = (size_t)blockIdx.x * 64;
    float acc[8];
#pragma unroll
    for (int n = 0; n < 8; n++) acc[n] = 0.0f;

    const float* H = BT<L>::H();
    for (int k = 0; k < KBINS; k++) {
        ((float4*)Ws)[tid] = __ldg(&((const float4*)(W + (size_t)k * 1024))[tid]);
#pragma unroll
        for (int r = 0; r < 2; r++) {
            int idx = tid + r * 256;
            int nd = idx >> 3, q = idx & 7;
            ((float4*)Hs)[idx] =
                *(const float4*)&H[((nodeBase + nd) * KBINS + k) * 32 + q * 4];
        }
        __syncthreads();
#pragma unroll
        for (int i4 = 0; i4 < 8; i4++) {
            float w0 = Ws[(i4 * 4 + 0) * 32 + lane];
            float w1 = Ws[(i4 * 4 + 1) * 32 + lane];
            float w2 = Ws[(i4 * 4 + 2) * 32 + lane];
            float w3 = Ws[(i4 * 4 + 3) * 32 + lane];
#pragma unroll
            for (int n = 0; n < 8; n++) {
                float4 hv = ((float4*)Hs)[(w * 8 + n) * 8 + i4];
                acc[n] += hv.x * w0 + hv.y * w1 + hv.z * w2 + hv.w * w3;
            }
        }
        __syncthreads();
    }
    // divide by degree
#pragma unroll
    for (int n = 0; n < 8; n++) {
        int node = (int)nodeBase + w * 8 + n;
        int deg = BT<L>::off()[node + 1] - BT<L>::off()[node];
        acc[n] /= (float)(deg > 0 ? deg : 1);
    }
    // root term: reuse the same machinery with W=root, H=hin
    ((float4*)Ws)[tid] = __ldg(&((const float4*)root)[tid]);
    const float* hin = BT<L>::hin();
#pragma unroll
    for (int r = 0; r < 2; r++) {
        int idx = tid + r * 256;
        int nd = idx >> 3, q = idx & 7;
        ((float4*)Hs)[idx] = *(const float4*)&hin[(nodeBase + nd) * 32 + q * 4];
    }
    __syncthreads();
#pragma unroll
    for (int i4 = 0; i4 < 8; i4++) {
        float w0 = Ws[(i4 * 4 + 0) * 32 + lane];
        float w1 = Ws[(i4 * 4 + 1) * 32 + lane];
        float w2 = Ws[(i4 * 4 + 2) * 32 + lane];
        float w3 = Ws[(i4 * 4 + 3) * 32 + lane];
#pragma unroll
        for (int n = 0; n < 8; n++) {
            float4 hv = ((float4*)Hs)[(w * 8 + n) * 8 + i4];
            acc[n] += hv.x * w0 + hv.y * w1 + hv.z * w2 + hv.w * w3;
        }
    }
    float bv = __ldg(&bias[lane]);
    float* hout = BT<L>::hout();
#pragma unroll
    for (int n = 0; n < 8; n++) {
        float v = acc[n] + bv;
        hout[(nodeBase + w * 8 + n) * 32 + lane] = v > 0.0f ? v : expm1f(v);
    }
}

// ---------------- FC head + log_softmax ----------------
__global__ void k_fc_head(const float* __restrict__ fcw, const float* __restrict__ fcb,
                          float* __restrict__ out) {
    __shared__ float hs[256];
    __shared__ float lg[10];
    __shared__ float lse;
    int b = blockIdx.x;
    int t = threadIdx.x;
    hs[t] = g_p3[(size_t)b * 256 + t];
    __syncthreads();
    if (t < 10) {
        float s = __ldg(&fcb[t]);
#pragma unroll 8
        for (int i = 0; i < 256; i++) s += hs[i] * __ldg(&fcw[i * 10 + t]);
        lg[t] = s;
    }
    __syncthreads();
    if (t == 0) {
        float m = lg[0];
        for (int j = 1; j < 10; j++) m = fmaxf(m, lg[j]);
        float se = 0.0f;
        for (int j = 0; j < 10; j++) se += expf(lg[j] - m);
        lse = m + logf(se);
    }
    __syncthreads();
    if (t < 10) out[b * 10 + t] = lg[t] - lse;
}

// ---------------- launcher ----------------
static inline int cdiv(long long a, int b) { return (int)((a + b - 1) / b); }

extern "C" void kernel_launch(void* const* d_in, const int* in_sizes, int n_in,
                              void* d_out, int out_size) {
    const float* x        = (const float*)d_in[0];
    const int*   cluster0 = (const int*)d_in[1];
    const int*   ei1      = (const int*)d_in[2];
    const float* pseudo1  = (const float*)d_in[3];
    const int*   cluster1 = (const int*)d_in[4];
    const int*   ei2      = (const int*)d_in[5];
    const float* pseudo2  = (const float*)d_in[6];
    const int*   cluster2 = (const int*)d_in[7];
    const int*   ei3      = (const int*)d_in[8];
    const float* pseudo3  = (const float*)d_in[9];
    const int*   cluster3 = (const int*)d_in[10];
    const float* W1       = (const float*)d_in[11];
    const float* root1    = (const float*)d_in[12];
    const float* b1       = (const float*)d_in[13];
    const float* W2       = (const float*)d_in[14];
    const float* root2    = (const float*)d_in[15];
    const float* b2       = (const float*)d_in[16];
    const float* W3       = (const float*)d_in[17];
    const float* root3    = (const float*)d_in[18];
    const float* b3       = (const float*)d_in[19];
    const float* fcw      = (const float*)d_in[20];
    const float* fcb      = (const float*)d_in[21];
    float* out = (float*)d_out;

    const int TB = 256;

    k_init_all<<<512, TB>>>();

    // CSR builds (independent of pools)
    k_hist<1><<<cdiv(E1, TB), TB>>>(ei1);
    k_hist<2><<<cdiv(E2, TB), TB>>>(ei2);
    k_hist<3><<<cdiv(E3, TB), TB>>>(ei3);
    k_scan<1><<<1, 1024>>>();
    k_scan<2><<<1, 1024>>>();
    k_scan<3><<<1, 1024>>>();
    k_permscat<1><<<cdiv(E1, TB), TB>>>(ei1, pseudo1);
    k_permscat<2><<<cdiv(E2, TB), TB>>>(ei2, pseudo2);
    k_permscat<3><<<cdiv(E3, TB), TB>>>(ei3, pseudo3);

    // ---- level 1 ----
    k_pool0<<<cdiv(N0, TB), TB>>>(x, cluster0);
    k_fix0<<<cdiv(N1, TB), TB>>>();
    k_scatter1<<<N1 / 8, TB>>>();
    k_gemm1<<<N1 / 8, TB>>>(W1, root1, b1);

    // ---- level 2 ----
    k_pool32<1><<<cdiv(N1 * 32, TB), TB>>>(cluster1, N1);
    k_fix32<1><<<cdiv(N2 * 32, TB), TB>>>(N2 * 32);
    k_scatter32<2><<<N2 / 2, 64>>>();
    k_gemm32<2><<<N2 / 64, TB>>>(W2, root2, b2);

    // ---- level 3 ----
    k_pool32<2><<<cdiv(N2 * 32, TB), TB>>>(cluster2, N2);
    k_fix32<2><<<cdiv(N3 * 32, TB), TB>>>(N3 * 32);
    k_scatter32<3><<<N3 / 2, 64>>>();
    k_gemm32<3><<<N3 / 64, TB>>>(W3, root3, b3);

    // ---- final pool + FC ----
    k_pool32<3><<<cdiv(N3 * 32, TB), TB>>>(cluster3, N3);
    k_fix32<3><<<cdiv(B8 * 32, TB), TB>>>(B8 * 32);
    k_fc_head<<<NBATCH, 256>>>(fcw, fcb, out);
}